// round 1
// baseline (speedup 1.0000x reference)
#include <cuda_runtime.h>

// WindowAttention fused kernel: one CTA per window, fp32, FMA-bound by design.
// Phases: load x -> QKV gemm (w tiles staged transposed in smem) -> QK^T+bias+mask
// -> softmax -> AV -> proj gemm -> store.

#define WSZ   7
#define NTOK  49
#define DIMC  128
#define NHEAD 4
#define HDIM  32
#define NWIN  64

#define NPAD  52   // attn row pad (16B-aligned rows, no conflicts)
#define KTPAD 53   // k-transposed pad (odd -> conflict-free strided stores)
#define WTPAD 65   // weight-tile pad (odd -> conflict-free strided stores)

// smem layout (floats)
#define OFF_XS 0                          // x / later y: 49*128 = 6272
#define OFF_WT (OFF_XS + NTOK*DIMC)       // wt[128][65]  = 8320
#define OFF_QS (OFF_WT + DIMC*WTPAD)      // q[49][128]   = 6272
#define OFF_KT (OFF_QS + NTOK*DIMC)       // kt[128][53]  = 6784
#define OFF_VS (OFF_KT + DIMC*KTPAD)      // v[49][128]   = 6272
#define OFF_AT (OFF_VS + NTOK*DIMC)       // attn[4][49][52] = 10192
#define SMEM_FLOATS (OFF_AT + NHEAD*NTOK*NPAD)   // 44112 floats = 176448 B

__global__ void __launch_bounds__(256, 1)
swin_attn_kernel(const float* __restrict__ x,
                 const float* __restrict__ attn_mask,
                 const float* __restrict__ qkv_w,
                 const float* __restrict__ qkv_b,
                 const float* __restrict__ proj_w,
                 const float* __restrict__ proj_b,
                 const float* __restrict__ rpb_table,
                 const int*   __restrict__ rpb_index,
                 float*       __restrict__ out)
{
    extern __shared__ float smem[];
    float* xs = smem + OFF_XS;
    float* wt = smem + OFF_WT;
    float* qs = smem + OFF_QS;
    float* kt = smem + OFF_KT;
    float* vs = smem + OFF_VS;
    float* at = smem + OFF_AT;

    const int t   = threadIdx.x;
    const int bnw = blockIdx.x;
    const int win = bnw & (NWIN - 1);

    // ---------------- load x tile [49][128] (float4, coalesced) ----------------
    {
        const float4* xg  = (const float4*)(x + (size_t)bnw * NTOK * DIMC);
        float4*       xs4 = (float4*)xs;
        #pragma unroll 4
        for (int i = t; i < NTOK * DIMC / 4; i += 256) xs4[i] = xg[i];
    }
    __syncthreads();

    const int j  = t & 63;   // output column within 64-wide tile
    const int ib = t >> 6;   // row group 0..3 (rows i = ib, ib+4, ...)

    // ---------------- QKV gemm: 6 tiles of 64 cols, K=128 ----------------
    for (int tile = 0; tile < 6; ++tile) {
        // stage weight tile transposed: wt[k][j] (conflict-free both directions)
        {
            const float* wg = qkv_w + tile * 64 * DIMC;
            #pragma unroll 4
            for (int idx = t; idx < 64 * DIMC; idx += 256) {
                int k = idx & 127, jj = idx >> 7;
                wt[k * WTPAD + jj] = wg[jj * DIMC + k];
            }
        }
        __syncthreads();

        float acc[13];
        #pragma unroll
        for (int r = 0; r < 13; ++r) acc[r] = 0.f;

        #pragma unroll 4
        for (int k4 = 0; k4 < DIMC; k4 += 4) {
            float w0 = wt[(k4 + 0) * WTPAD + j];
            float w1 = wt[(k4 + 1) * WTPAD + j];
            float w2 = wt[(k4 + 2) * WTPAD + j];
            float w3 = wt[(k4 + 3) * WTPAD + j];
            #pragma unroll
            for (int r = 0; r < 13; ++r) {
                int i = ib + 4 * r;                         // up to 51: stays in smem, unused rows never stored
                float4 xv = *(const float4*)&xs[i * DIMC + k4];  // full-warp broadcast
                acc[r] = fmaf(xv.x, w0, acc[r]);
                acc[r] = fmaf(xv.y, w1, acc[r]);
                acc[r] = fmaf(xv.z, w2, acc[r]);
                acc[r] = fmaf(xv.w, w3, acc[r]);
            }
        }

        const int col = tile * 64 + j;           // 0..383
        const float b = qkv_b[col];
        #pragma unroll
        for (int r = 0; r < 13; ++r) {
            int i = ib + 4 * r;
            if (i < NTOK) {
                float val = acc[r] + b;
                if (col < DIMC)            qs[i * DIMC + col] = val;
                else if (col < 2 * DIMC)   kt[(col - DIMC) * KTPAD + i] = val;   // K transposed
                else                       vs[i * DIMC + (col - 2 * DIMC)] = val;
            }
        }
        __syncthreads();   // wt reused next tile
    }

    // ---------------- QK^T * scale + bias + mask ----------------
    const float scale = 0.17677669529663687f;   // 32^-0.5
    const float* mrow = attn_mask + (size_t)win * NTOK * NTOK;
    for (int h = 0; h < NHEAD; ++h) {
        if (j < NTOK) {
            float acc[13];
            #pragma unroll
            for (int r = 0; r < 13; ++r) acc[r] = 0.f;

            #pragma unroll
            for (int d4 = 0; d4 < HDIM; d4 += 4) {
                float k0 = kt[(h * HDIM + d4 + 0) * KTPAD + j];
                float k1 = kt[(h * HDIM + d4 + 1) * KTPAD + j];
                float k2 = kt[(h * HDIM + d4 + 2) * KTPAD + j];
                float k3 = kt[(h * HDIM + d4 + 3) * KTPAD + j];
                #pragma unroll
                for (int r = 0; r < 13; ++r) {
                    int i = ib + 4 * r;
                    float4 qv = *(const float4*)&qs[i * DIMC + h * HDIM + d4];  // broadcast
                    acc[r] = fmaf(qv.x, k0, acc[r]);
                    acc[r] = fmaf(qv.y, k1, acc[r]);
                    acc[r] = fmaf(qv.z, k2, acc[r]);
                    acc[r] = fmaf(qv.w, k3, acc[r]);
                }
            }
            #pragma unroll
            for (int r = 0; r < 13; ++r) {
                int i = ib + 4 * r;
                if (i < NTOK) {
                    int ij = i * NTOK + j;
                    float bias = rpb_table[rpb_index[ij] * NHEAD + h];
                    at[(h * NTOK + i) * NPAD + j] = acc[r] * scale + bias + mrow[ij];
                }
            }
        }
    }
    __syncthreads();

    // ---------------- softmax over last dim (49), one warp per row ----------------
    {
        const int warp = t >> 5, lane = t & 31;
        for (int r = warp; r < NHEAD * NTOK; r += 8) {
            float* row = at + r * NPAD;
            float a0 = row[lane];
            float a1 = (lane + 32 < NTOK) ? row[lane + 32] : -1e30f;
            float m = fmaxf(a0, a1);
            #pragma unroll
            for (int o = 16; o; o >>= 1) m = fmaxf(m, __shfl_xor_sync(~0u, m, o));
            float e0 = __expf(a0 - m);
            float e1 = (lane + 32 < NTOK) ? __expf(a1 - m) : 0.f;
            float s = e0 + e1;
            #pragma unroll
            for (int o = 16; o; o >>= 1) s += __shfl_xor_sync(~0u, s, o);
            float inv = 1.f / s;
            row[lane] = e0 * inv;
            if (lane + 32 < NTOK) row[lane + 32] = e1 * inv;
        }
    }
    __syncthreads();

    // ---------------- AV: y[i][c] = sum_j attn[h][i][j] * v[j][c]  (y -> xs) ----------------
    {
        const int c  = t & 127;
        const int ig = t >> 7;          // rows i = ig, ig+2, ...
        const int h  = c >> 5;
        float acc[25];
        #pragma unroll
        for (int r = 0; r < 25; ++r) acc[r] = 0.f;

        #pragma unroll 3
        for (int j4 = 0; j4 < 48; j4 += 4) {
            float v0 = vs[(j4 + 0) * DIMC + c];
            float v1 = vs[(j4 + 1) * DIMC + c];
            float v2 = vs[(j4 + 2) * DIMC + c];
            float v3 = vs[(j4 + 3) * DIMC + c];
            #pragma unroll
            for (int r = 0; r < 25; ++r) {
                int i = min(ig + 2 * r, NTOK - 1);                        // clamp: stay in at[]
                float4 a4 = *(const float4*)&at[(h * NTOK + i) * NPAD + j4];  // broadcast
                acc[r] = fmaf(a4.x, v0, acc[r]);
                acc[r] = fmaf(a4.y, v1, acc[r]);
                acc[r] = fmaf(a4.z, v2, acc[r]);
                acc[r] = fmaf(a4.w, v3, acc[r]);
            }
        }
        {   // tail j = 48
            float v48 = vs[48 * DIMC + c];
            #pragma unroll
            for (int r = 0; r < 25; ++r) {
                int i = min(ig + 2 * r, NTOK - 1);
                acc[r] = fmaf(at[(h * NTOK + i) * NPAD + 48], v48, acc[r]);
            }
        }
        #pragma unroll
        for (int r = 0; r < 25; ++r) {
            int i = ig + 2 * r;
            if (i < NTOK) xs[i * DIMC + c] = acc[r];   // x is dead; reuse as y
        }
    }
    __syncthreads();

    // ---------------- proj gemm: 2 tiles of 64 cols, K=128, y=xs ----------------
    float* og = out + (size_t)bnw * NTOK * DIMC;
    for (int tile = 0; tile < 2; ++tile) {
        {
            const float* wg = proj_w + tile * 64 * DIMC;
            #pragma unroll 4
            for (int idx = t; idx < 64 * DIMC; idx += 256) {
                int k = idx & 127, jj = idx >> 7;
                wt[k * WTPAD + jj] = wg[jj * DIMC + k];
            }
        }
        __syncthreads();

        float acc[13];
        #pragma unroll
        for (int r = 0; r < 13; ++r) acc[r] = 0.f;

        #pragma unroll 4
        for (int k4 = 0; k4 < DIMC; k4 += 4) {
            float w0 = wt[(k4 + 0) * WTPAD + j];
            float w1 = wt[(k4 + 1) * WTPAD + j];
            float w2 = wt[(k4 + 2) * WTPAD + j];
            float w3 = wt[(k4 + 3) * WTPAD + j];
            #pragma unroll
            for (int r = 0; r < 13; ++r) {
                int i = ib + 4 * r;
                float4 yv = *(const float4*)&xs[i * DIMC + k4];
                acc[r] = fmaf(yv.x, w0, acc[r]);
                acc[r] = fmaf(yv.y, w1, acc[r]);
                acc[r] = fmaf(yv.z, w2, acc[r]);
                acc[r] = fmaf(yv.w, w3, acc[r]);
            }
        }

        const int col = tile * 64 + j;
        const float b = proj_b[col];
        #pragma unroll
        for (int r = 0; r < 13; ++r) {
            int i = ib + 4 * r;
            if (i < NTOK) og[i * DIMC + col] = acc[r] + b;   // lanes j-contiguous: coalesced
        }
        __syncthreads();
    }
}

extern "C" void kernel_launch(void* const* d_in, const int* in_sizes, int n_in,
                              void* d_out, int out_size)
{
    const float* x         = (const float*)d_in[0];
    const float* attn_mask = (const float*)d_in[1];
    const float* qkv_w     = (const float*)d_in[2];
    const float* qkv_b     = (const float*)d_in[3];
    const float* proj_w    = (const float*)d_in[4];
    const float* proj_b    = (const float*)d_in[5];
    const float* rpb_table = (const float*)d_in[6];
    const int*   rpb_index = (const int*)d_in[7];
    float*       out       = (float*)d_out;

    const int bnw = in_sizes[0] / (NTOK * DIMC);   // 8192
    const int smem_bytes = SMEM_FLOATS * (int)sizeof(float);

    cudaFuncSetAttribute(swin_attn_kernel,
                         cudaFuncAttributeMaxDynamicSharedMemorySize, smem_bytes);

    swin_attn_kernel<<<bnw, 256, smem_bytes>>>(
        x, attn_mask, qkv_w, qkv_b, proj_w, proj_b, rpb_table, rpb_index, out);
}

// round 3
// speedup vs baseline: 1.7443x; 1.7443x over previous
#include <cuda_runtime.h>

// WindowAttention fused: one CTA per window, 512 threads (16 warps), fp32.
// R2: doubled warps for latency hiding + 2-col register blocking in QKV/proj.

#define WSZ   7
#define NTOK  49
#define DIMC  128
#define NHEAD 4
#define HDIM  32
#define NWIN  64

#define NPAD  52    // attn row pad
#define KTPAD 53    // k-transposed pad
#define WTPAD 129   // weight-tile pad (odd -> conflict-free strided stores)

// smem layout (floats)
#define OFF_XS 0                          // x / later y: 49*128 = 6272
#define OFF_WT (OFF_XS + NTOK*DIMC)       // wt[128][129] = 16512
#define OFF_QS (OFF_WT + DIMC*WTPAD)      // q[49][128]   = 6272
#define OFF_KT (OFF_QS + NTOK*DIMC)       // kt[128][53]  = 6784
#define OFF_VS (OFF_KT + DIMC*KTPAD)      // v[49][128]   = 6272
#define OFF_AT (OFF_VS + NTOK*DIMC)       // attn[4][49][52] = 10192
#define SMEM_FLOATS (OFF_AT + NHEAD*NTOK*NPAD)   // 52304 floats = 209216 B

#define NTHREADS 512

__global__ void __launch_bounds__(NTHREADS, 1)
swin_attn_kernel(const float* __restrict__ x,
                 const float* __restrict__ attn_mask,
                 const float* __restrict__ qkv_w,
                 const float* __restrict__ qkv_b,
                 const float* __restrict__ proj_w,
                 const float* __restrict__ proj_b,
                 const float* __restrict__ rpb_table,
                 const int*   __restrict__ rpb_index,
                 float*       __restrict__ out)
{
    extern __shared__ float smem[];
    float* xs = smem + OFF_XS;
    float* wt = smem + OFF_WT;
    float* qs = smem + OFF_QS;
    float* kt = smem + OFF_KT;
    float* vs = smem + OFF_VS;
    float* at = smem + OFF_AT;

    const int t   = threadIdx.x;
    const int bnw = blockIdx.x;
    const int win = bnw & (NWIN - 1);

    // ---------------- load x tile [49][128] ----------------
    {
        const float4* xg  = (const float4*)(x + (size_t)bnw * NTOK * DIMC);
        float4*       xs4 = (float4*)xs;
        #pragma unroll
        for (int i = t; i < NTOK * DIMC / 4; i += NTHREADS) xs4[i] = xg[i];
    }
    __syncthreads();

    const int j0 = t & 63;    // first output col in 128-wide tile (second = j0+64)
    const int ib = t >> 6;    // row group 0..7 (rows i = ib + 8r, r<7)

    // ---------------- QKV gemm: 3 tiles of 128 cols, K=128 ----------------
    for (int tile = 0; tile < 3; ++tile) {
        {   // stage weight tile transposed: wt[k][jj]
            const float* wg = qkv_w + tile * 128 * DIMC;
            #pragma unroll
            for (int idx = t; idx < 128 * DIMC; idx += NTHREADS) {
                int k = idx & 127, jj = idx >> 7;
                wt[k * WTPAD + jj] = wg[jj * DIMC + k];   // gmem coalesced, smem conflict-free
            }
        }
        __syncthreads();

        float acc0[7], acc1[7];
        #pragma unroll
        for (int r = 0; r < 7; ++r) { acc0[r] = 0.f; acc1[r] = 0.f; }

        #pragma unroll 4
        for (int k4 = 0; k4 < DIMC; k4 += 4) {
            float wa0 = wt[(k4 + 0) * WTPAD + j0];
            float wa1 = wt[(k4 + 1) * WTPAD + j0];
            float wa2 = wt[(k4 + 2) * WTPAD + j0];
            float wa3 = wt[(k4 + 3) * WTPAD + j0];
            float wb0 = wt[(k4 + 0) * WTPAD + j0 + 64];
            float wb1 = wt[(k4 + 1) * WTPAD + j0 + 64];
            float wb2 = wt[(k4 + 2) * WTPAD + j0 + 64];
            float wb3 = wt[(k4 + 3) * WTPAD + j0 + 64];
            #pragma unroll
            for (int r = 0; r < 7; ++r) {
                int i = ib + 8 * r;                              // up to 55: in-smem garbage reads OK
                float4 xv = *(const float4*)&xs[i * DIMC + k4];  // warp broadcast
                acc0[r] = fmaf(xv.x, wa0, acc0[r]);
                acc0[r] = fmaf(xv.y, wa1, acc0[r]);
                acc0[r] = fmaf(xv.z, wa2, acc0[r]);
                acc0[r] = fmaf(xv.w, wa3, acc0[r]);
                acc1[r] = fmaf(xv.x, wb0, acc1[r]);
                acc1[r] = fmaf(xv.y, wb1, acc1[r]);
                acc1[r] = fmaf(xv.z, wb2, acc1[r]);
                acc1[r] = fmaf(xv.w, wb3, acc1[r]);
            }
        }

        const float b0 = qkv_b[tile * 128 + j0];
        const float b1 = qkv_b[tile * 128 + j0 + 64];
        #pragma unroll
        for (int r = 0; r < 7; ++r) {
            int i = ib + 8 * r;
            if (i < NTOK) {
                float v0 = acc0[r] + b0;
                float v1 = acc1[r] + b1;
                if (tile == 0)      { qs[i * DIMC + j0] = v0;           qs[i * DIMC + j0 + 64] = v1; }
                else if (tile == 1) { kt[j0 * KTPAD + i] = v0;          kt[(j0 + 64) * KTPAD + i] = v1; }
                else                { vs[i * DIMC + j0] = v0;           vs[i * DIMC + j0 + 64] = v1; }
            }
        }
        __syncthreads();
    }

    // ---------------- QK^T * scale + bias + mask ----------------
    {
        const float scale = 0.17677669529663687f;  // 32^-0.5
        const float* mrow = attn_mask + (size_t)win * NTOK * NTOK;
        const int h   = t >> 7;          // 0..3
        const int ib2 = (t >> 6) & 1;    // rows i = ib2 + 2r, r<25
        const int j   = t & 63;
        if (j < NTOK) {
            float acc[25];
            #pragma unroll
            for (int r = 0; r < 25; ++r) acc[r] = 0.f;

            #pragma unroll
            for (int d4 = 0; d4 < HDIM; d4 += 4) {
                float k0 = kt[(h * HDIM + d4 + 0) * KTPAD + j];
                float k1 = kt[(h * HDIM + d4 + 1) * KTPAD + j];
                float k2 = kt[(h * HDIM + d4 + 2) * KTPAD + j];
                float k3 = kt[(h * HDIM + d4 + 3) * KTPAD + j];
                #pragma unroll
                for (int r = 0; r < 25; ++r) {
                    int i = min(ib2 + 2 * r, NTOK - 1);
                    float4 qv = *(const float4*)&qs[i * DIMC + h * HDIM + d4];  // broadcast
                    acc[r] = fmaf(qv.x, k0, acc[r]);
                    acc[r] = fmaf(qv.y, k1, acc[r]);
                    acc[r] = fmaf(qv.z, k2, acc[r]);
                    acc[r] = fmaf(qv.w, k3, acc[r]);
                }
            }
            #pragma unroll
            for (int r = 0; r < 25; ++r) {
                int i = ib2 + 2 * r;
                if (i < NTOK) {
                    int ij = i * NTOK + j;
                    float bias = rpb_table[rpb_index[ij] * NHEAD + h];
                    at[(h * NTOK + i) * NPAD + j] = acc[r] * scale + bias + mrow[ij];
                }
            }
        }
    }
    __syncthreads();

    // ---------------- softmax over last dim (49), one warp per row ----------------
    {
        const int warp = t >> 5, lane = t & 31;
        for (int r = warp; r < NHEAD * NTOK; r += 16) {
            float* row = at + r * NPAD;
            float a0 = row[lane];
            float a1 = (lane + 32 < NTOK) ? row[lane + 32] : -1e30f;
            float m = fmaxf(a0, a1);
            #pragma unroll
            for (int o = 16; o; o >>= 1) m = fmaxf(m, __shfl_xor_sync(~0u, m, o));
            float e0 = __expf(a0 - m);
            float e1 = (lane + 32 < NTOK) ? __expf(a1 - m) : 0.f;
            float s = e0 + e1;
            #pragma unroll
            for (int o = 16; o; o >>= 1) s += __shfl_xor_sync(~0u, s, o);
            float inv = 1.f / s;
            row[lane] = e0 * inv;
            if (lane + 32 < NTOK) row[lane + 32] = e1 * inv;
        }
    }
    __syncthreads();

    // ---------------- AV: y[i][c] = sum_j attn[h][i][j] * v[j][c]  (y -> xs) ----------------
    {
        const int c  = t & 127;
        const int ig = t >> 7;           // rows i = ig + 4r, r<13
        const int h  = c >> 5;
        float acc[13];
        #pragma unroll
        for (int r = 0; r < 13; ++r) acc[r] = 0.f;

        #pragma unroll 3
        for (int j4 = 0; j4 < 48; j4 += 4) {
            float v0 = vs[(j4 + 0) * DIMC + c];
            float v1 = vs[(j4 + 1) * DIMC + c];
            float v2 = vs[(j4 + 2) * DIMC + c];
            float v3 = vs[(j4 + 3) * DIMC + c];
            #pragma unroll
            for (int r = 0; r < 13; ++r) {
                int i = min(ig + 4 * r, NTOK - 1);
                float4 a4 = *(const float4*)&at[(h * NTOK + i) * NPAD + j4];  // broadcast
                acc[r] = fmaf(a4.x, v0, acc[r]);
                acc[r] = fmaf(a4.y, v1, acc[r]);
                acc[r] = fmaf(a4.z, v2, acc[r]);
                acc[r] = fmaf(a4.w, v3, acc[r]);
            }
        }
        {   // tail j = 48
            float v48 = vs[48 * DIMC + c];
            #pragma unroll
            for (int r = 0; r < 13; ++r) {
                int i = min(ig + 4 * r, NTOK - 1);
                acc[r] = fmaf(at[(h * NTOK + i) * NPAD + 48], v48, acc[r]);
            }
        }
        __syncthreads();                 // vs/at reads done before xs overwrite? (xs distinct, but keep order w.r.t. next phase)
        #pragma unroll
        for (int r = 0; r < 13; ++r) {
            int i = ig + 4 * r;
            if (i < NTOK) xs[i * DIMC + c] = acc[r];   // reuse xs as y
        }
    }
    __syncthreads();

    // ---------------- proj gemm: 1 tile of 128 cols, K=128, y=xs ----------------
    {
        #pragma unroll
        for (int idx = t; idx < 128 * DIMC; idx += NTHREADS) {
            int k = idx & 127, jj = idx >> 7;
            wt[k * WTPAD + jj] = proj_w[jj * DIMC + k];
        }
        __syncthreads();

        float acc0[7], acc1[7];
        #pragma unroll
        for (int r = 0; r < 7; ++r) { acc0[r] = 0.f; acc1[r] = 0.f; }

        #pragma unroll 4
        for (int k4 = 0; k4 < DIMC; k4 += 4) {
            float wa0 = wt[(k4 + 0) * WTPAD + j0];
            float wa1 = wt[(k4 + 1) * WTPAD + j0];
            float wa2 = wt[(k4 + 2) * WTPAD + j0];
            float wa3 = wt[(k4 + 3) * WTPAD + j0];
            float wb0 = wt[(k4 + 0) * WTPAD + j0 + 64];
            float wb1 = wt[(k4 + 1) * WTPAD + j0 + 64];
            float wb2 = wt[(k4 + 2) * WTPAD + j0 + 64];
            float wb3 = wt[(k4 + 3) * WTPAD + j0 + 64];
            #pragma unroll
            for (int r = 0; r < 7; ++r) {
                int i = ib + 8 * r;
                float4 yv = *(const float4*)&xs[i * DIMC + k4];
                acc0[r] = fmaf(yv.x, wa0, acc0[r]);
                acc0[r] = fmaf(yv.y, wa1, acc0[r]);
                acc0[r] = fmaf(yv.z, wa2, acc0[r]);
                acc0[r] = fmaf(yv.w, wa3, acc0[r]);
                acc1[r] = fmaf(yv.x, wb0, acc1[r]);
                acc1[r] = fmaf(yv.y, wb1, acc1[r]);
                acc1[r] = fmaf(yv.z, wb2, acc1[r]);
                acc1[r] = fmaf(yv.w, wb3, acc1[r]);
            }
        }

        float* og = out + (size_t)bnw * NTOK * DIMC;
        const float b0 = proj_b[j0];
        const float b1 = proj_b[j0 + 64];
        #pragma unroll
        for (int r = 0; r < 7; ++r) {
            int i = ib + 8 * r;
            if (i < NTOK) {
                og[i * DIMC + j0]      = acc0[r] + b0;   // lanes contiguous: coalesced
                og[i * DIMC + j0 + 64] = acc1[r] + b1;
            }
        }
    }
}

extern "C" void kernel_launch(void* const* d_in, const int* in_sizes, int n_in,
                              void* d_out, int out_size)
{
    const float* x         = (const float*)d_in[0];
    const float* attn_mask = (const float*)d_in[1];
    const float* qkv_w     = (const float*)d_in[2];
    const float* qkv_b     = (const float*)d_in[3];
    const float* proj_w    = (const float*)d_in[4];
    const float* proj_b    = (const float*)d_in[5];
    const float* rpb_table = (const float*)d_in[6];
    const int*   rpb_index = (const int*)d_in[7];
    float*       out       = (float*)d_out;

    const int bnw = in_sizes[0] / (NTOK * DIMC);   // 8192
    const int smem_bytes = SMEM_FLOATS * (int)sizeof(float);

    cudaFuncSetAttribute(swin_attn_kernel,
                         cudaFuncAttributeMaxDynamicSharedMemorySize, smem_bytes);

    swin_attn_kernel<<<bnw, NTHREADS, smem_bytes>>>(
        x, attn_mask, qkv_w, qkv_b, proj_w, proj_b, rpb_table, rpb_index, out);
}

// round 6
// speedup vs baseline: 2.5152x; 1.4420x over previous
#include <cuda_runtime.h>
#include <cuda_bf16.h>
#include <cstdint>

// WindowAttention fused, R5: QKV + proj GEMMs on mma.sync bf16 (split hi/lo, 3 products),
// attention scalar fp32. One CTA per window, 512 threads. (tcgen05 unavailable: harness
// compiles compute_103 without the 'a' feature.)

#define NTOK  49
#define DIMC  128
#define NHEAD 4
#define HDIM  32
#define NWIN  64
#define NTHREADS 512

#define QPAD  132
#define KTPAD 53
#define NPAD  52

#define APITCH 272          // bytes per bf16 tile row (136 bf16; 17*16B -> ldmatrix conflict-free)

// smem byte layout
#define SM_AHI 0                         // A tile hi: 64 rows * 272 = 17408
#define SM_ALO (SM_AHI + 64*APITCH)
#define SM_BHI (SM_ALO + 64*APITCH)      // B tile hi: 128 rows * 272 = 34816
#define SM_BLO (SM_BHI + 128*APITCH)
#define SM_ENDB (SM_BLO + 128*APITCH)    // 104448
#define SM_AT  SM_BHI                    // attn[4][49][52] f32 = 40768, overlays B (dead then)
#define SM_QS  SM_ENDB                   // 49*132*4 = 25872
#define SM_KT  (SM_QS + NTOK*QPAD*4)     // 128*53*4 = 27136
#define SM_VS  (SM_KT + DIMC*KTPAD*4)    // 25872
#define SMEM_TOTAL (SM_VS + NTOK*QPAD*4) // 183328 B

__device__ __forceinline__ uint32_t smem_u32(const void* p) {
    uint32_t a;
    asm("{ .reg .u64 t; cvta.to.shared.u64 t, %1; cvt.u32.u64 %0, t; }" : "=r"(a) : "l"(p));
    return a;
}
__device__ __forceinline__ void ldsm4(uint32_t r[4], uint32_t a) {
    asm volatile("ldmatrix.sync.aligned.m8n8.x4.shared.b16 {%0,%1,%2,%3}, [%4];"
                 : "=r"(r[0]), "=r"(r[1]), "=r"(r[2]), "=r"(r[3]) : "r"(a));
}
__device__ __forceinline__ void mma16816(float c[4], const uint32_t a[4], uint32_t b0, uint32_t b1) {
    asm volatile("mma.sync.aligned.m16n8k16.row.col.f32.bf16.bf16.f32 "
                 "{%0,%1,%2,%3}, {%4,%5,%6,%7}, {%8,%9}, {%0,%1,%2,%3};"
                 : "+f"(c[0]), "+f"(c[1]), "+f"(c[2]), "+f"(c[3])
                 : "r"(a[0]), "r"(a[1]), "r"(a[2]), "r"(a[3]), "r"(b0), "r"(b1));
}

__device__ __forceinline__ void split_store(float v, char* hi, char* lo, uint32_t off) {
    __nv_bfloat16 h = __float2bfloat16(v);
    *(__nv_bfloat16*)(hi + off) = h;
    *(__nv_bfloat16*)(lo + off) = __float2bfloat16(v - __bfloat162float(h));
}
__device__ __forceinline__ void split_store4(float4 v, char* hi, char* lo, int r, int c) {
    uint32_t o = (uint32_t)(r * APITCH + c * 2);
    __nv_bfloat16 h0 = __float2bfloat16(v.x), h1 = __float2bfloat16(v.y);
    __nv_bfloat16 h2 = __float2bfloat16(v.z), h3 = __float2bfloat16(v.w);
    *(__nv_bfloat162*)(hi + o)     = __nv_bfloat162(h0, h1);
    *(__nv_bfloat162*)(hi + o + 4) = __nv_bfloat162(h2, h3);
    __nv_bfloat16 l0 = __float2bfloat16(v.x - __bfloat162float(h0));
    __nv_bfloat16 l1 = __float2bfloat16(v.y - __bfloat162float(h1));
    __nv_bfloat16 l2 = __float2bfloat16(v.z - __bfloat162float(h2));
    __nv_bfloat16 l3 = __float2bfloat16(v.w - __bfloat162float(h3));
    *(__nv_bfloat162*)(lo + o)     = __nv_bfloat162(l0, l1);
    *(__nv_bfloat162*)(lo + o + 4) = __nv_bfloat162(l2, l3);
}

// warp-level GEMM: C[64x128] += A[64x128] * B[128x128]^T with split-bf16 3-product scheme.
// 8 warps, each m32n32. acc[2][4][4].
__device__ __forceinline__ void hmma_gemm(uint32_t sb, int wid, int lane, float acc[2][4][4]) {
    const int m0 = (wid >> 2) * 32;
    const int n0 = (wid & 3) * 32;
    const uint32_t aoff = (uint32_t)((m0 + (lane & 15)) * APITCH + ((lane & 16) >> 1) * 2);
    const uint32_t boff = (uint32_t)((n0 + (lane & 7)) * APITCH + ((lane >> 3) << 3) * 2);
    const uint32_t aHi = sb + SM_AHI + aoff, aLo = sb + SM_ALO + aoff;
    const uint32_t bHi = sb + SM_BHI + boff, bLo = sb + SM_BLO + boff;

    #pragma unroll
    for (int kk = 0; kk < 4; ++kk) {
        const int k0 = kk * 32;
        uint32_t bh[4][4], bl[4][4];
        #pragma unroll
        for (int ni = 0; ni < 4; ++ni) {
            ldsm4(bh[ni], bHi + ni * 8 * APITCH + k0 * 2);
            ldsm4(bl[ni], bLo + ni * 8 * APITCH + k0 * 2);
        }
        #pragma unroll
        for (int half = 0; half < 2; ++half) {
            const int k16 = k0 + half * 16;
            uint32_t ah[2][4], al[2][4];
            ldsm4(ah[0], aHi + k16 * 2);
            ldsm4(ah[1], aHi + 16 * APITCH + k16 * 2);
            ldsm4(al[0], aLo + k16 * 2);
            ldsm4(al[1], aLo + 16 * APITCH + k16 * 2);
            #pragma unroll
            for (int mi = 0; mi < 2; ++mi)
                #pragma unroll
                for (int ni = 0; ni < 4; ++ni) {
                    uint32_t b0 = bh[ni][2 * half], b1 = bh[ni][2 * half + 1];
                    mma16816(acc[mi][ni], ah[mi], b0, b1);
                    mma16816(acc[mi][ni], al[mi], b0, b1);
                    mma16816(acc[mi][ni], ah[mi], bl[ni][2 * half], bl[ni][2 * half + 1]);
                }
        }
    }
}

__global__ void __launch_bounds__(NTHREADS, 1)
swin_attn_kernel(const float* __restrict__ x,
                 const float* __restrict__ attn_mask,
                 const float* __restrict__ qkv_w,
                 const float* __restrict__ qkv_b,
                 const float* __restrict__ proj_w,
                 const float* __restrict__ proj_b,
                 const float* __restrict__ rpb_table,
                 const int*   __restrict__ rpb_index,
                 float*       __restrict__ out)
{
    extern __shared__ char smem[];
    const uint32_t sb = smem_u32(smem);
    char* a_hi = smem + SM_AHI;
    char* a_lo = smem + SM_ALO;
    char* b_hi = smem + SM_BHI;
    char* b_lo = smem + SM_BLO;
    float* qs = (float*)(smem + SM_QS);
    float* kt = (float*)(smem + SM_KT);
    float* vs = (float*)(smem + SM_VS);
    float* at = (float*)(smem + SM_AT);

    const int t = threadIdx.x, wid = t >> 5, lane = t & 31;
    const int bnw = blockIdx.x, win = bnw & (NWIN - 1);

    // ---- stage A = x (49x128) split bf16 ----
    {
        const float4* xg = (const float4*)(x + (size_t)bnw * NTOK * DIMC);
        for (int idx = t; idx < NTOK * DIMC / 4; idx += NTHREADS) {
            int r = idx >> 5, c = (idx & 31) << 2;
            split_store4(xg[idx], a_hi, a_lo, r, c);
        }
    }

    const int tr = lane >> 2, tc = (lane & 3) * 2;   // c-fragment coords

    // ---- QKV: 3 chunks of 128 output cols ----
    for (int chunk = 0; chunk < 3; ++chunk) {
        const float4* wg = (const float4*)(qkv_w + (size_t)chunk * 128 * DIMC);
        for (int idx = t; idx < 128 * DIMC / 4; idx += NTHREADS) {
            int r = idx >> 5, c = (idx & 31) << 2;
            split_store4(wg[idx], b_hi, b_lo, r, c);
        }
        __syncthreads();

        if (wid < 8) {
            float acc[2][4][4];
            #pragma unroll
            for (int mi = 0; mi < 2; ++mi)
                #pragma unroll
                for (int ni = 0; ni < 4; ++ni)
                    #pragma unroll
                    for (int q = 0; q < 4; ++q) acc[mi][ni][q] = 0.f;

            hmma_gemm(sb, wid, lane, acc);

            const int m0 = (wid >> 2) * 32, n0 = (wid & 3) * 32;
            #pragma unroll
            for (int mi = 0; mi < 2; ++mi)
                #pragma unroll
                for (int ni = 0; ni < 4; ++ni) {
                    int col = n0 + ni * 8 + tc;
                    float b0 = qkv_b[chunk * 128 + col];
                    float b1 = qkv_b[chunk * 128 + col + 1];
                    #pragma unroll
                    for (int h2 = 0; h2 < 2; ++h2) {
                        int m = m0 + mi * 16 + tr + h2 * 8;
                        if (m < NTOK) {
                            float v0 = acc[mi][ni][2 * h2]     + b0;
                            float v1 = acc[mi][ni][2 * h2 + 1] + b1;
                            if (chunk == 0) {
                                qs[m * QPAD + col] = v0; qs[m * QPAD + col + 1] = v1;
                            } else if (chunk == 1) {
                                kt[col * KTPAD + m] = v0; kt[(col + 1) * KTPAD + m] = v1;
                            } else {
                                vs[m * QPAD + col] = v0; vs[m * QPAD + col + 1] = v1;
                            }
                        }
                    }
                }
        }
        __syncthreads();
    }

    // ---- QK^T * scale + bias + mask (scalar fp32) ----
    {
        const float scale = 0.17677669529663687f;
        const float* mrow = attn_mask + (size_t)win * NTOK * NTOK;
        const int h = t >> 7, ib2 = (t >> 6) & 1, j = t & 63;
        if (j < NTOK) {
            float acc[25];
            #pragma unroll
            for (int r = 0; r < 25; ++r) acc[r] = 0.f;
            #pragma unroll
            for (int d4 = 0; d4 < HDIM; d4 += 4) {
                float k0 = kt[(h * HDIM + d4 + 0) * KTPAD + j];
                float k1 = kt[(h * HDIM + d4 + 1) * KTPAD + j];
                float k2 = kt[(h * HDIM + d4 + 2) * KTPAD + j];
                float k3 = kt[(h * HDIM + d4 + 3) * KTPAD + j];
                #pragma unroll
                for (int r = 0; r < 25; ++r) {
                    int i = min(ib2 + 2 * r, NTOK - 1);
                    float4 qv = *(const float4*)&qs[i * QPAD + h * HDIM + d4];
                    acc[r] = fmaf(qv.x, k0, acc[r]);
                    acc[r] = fmaf(qv.y, k1, acc[r]);
                    acc[r] = fmaf(qv.z, k2, acc[r]);
                    acc[r] = fmaf(qv.w, k3, acc[r]);
                }
            }
            #pragma unroll
            for (int r = 0; r < 25; ++r) {
                int i = ib2 + 2 * r;
                if (i < NTOK) {
                    int ij = i * NTOK + j;
                    float bias = rpb_table[rpb_index[ij] * NHEAD + h];
                    at[(h * NTOK + i) * NPAD + j] = acc[r] * scale + bias + mrow[ij];
                }
            }
        }
    }
    __syncthreads();

    // ---- softmax over 49 ----
    for (int r = wid; r < NHEAD * NTOK; r += 16) {
        float* row = at + r * NPAD;
        float a0 = row[lane];
        float a1 = (lane + 32 < NTOK) ? row[lane + 32] : -1e30f;
        float m = fmaxf(a0, a1);
        #pragma unroll
        for (int o = 16; o; o >>= 1) m = fmaxf(m, __shfl_xor_sync(~0u, m, o));
        float e0 = __expf(a0 - m);
        float e1 = (lane + 32 < NTOK) ? __expf(a1 - m) : 0.f;
        float s = e0 + e1;
        #pragma unroll
        for (int o = 16; o; o >>= 1) s += __shfl_xor_sync(~0u, s, o);
        float inv = 1.f / s;
        row[lane] = e0 * inv;
        if (lane + 32 < NTOK) row[lane + 32] = e1 * inv;
    }
    __syncthreads();

    // ---- AV (scalar) -> y split-stored into A tiles ----
    {
        const int c = t & 127, ig = t >> 7, h = c >> 5;
        float acc[13];
        #pragma unroll
        for (int r = 0; r < 13; ++r) acc[r] = 0.f;
        #pragma unroll 3
        for (int j4 = 0; j4 < 48; j4 += 4) {
            float v0 = vs[(j4 + 0) * QPAD + c];
            float v1 = vs[(j4 + 1) * QPAD + c];
            float v2 = vs[(j4 + 2) * QPAD + c];
            float v3 = vs[(j4 + 3) * QPAD + c];
            #pragma unroll
            for (int r = 0; r < 13; ++r) {
                int i = min(ig + 4 * r, NTOK - 1);
                float4 a4 = *(const float4*)&at[(h * NTOK + i) * NPAD + j4];
                acc[r] = fmaf(a4.x, v0, acc[r]);
                acc[r] = fmaf(a4.y, v1, acc[r]);
                acc[r] = fmaf(a4.z, v2, acc[r]);
                acc[r] = fmaf(a4.w, v3, acc[r]);
            }
        }
        {
            float v48 = vs[48 * QPAD + c];
            #pragma unroll
            for (int r = 0; r < 13; ++r) {
                int i = min(ig + 4 * r, NTOK - 1);
                acc[r] = fmaf(at[(h * NTOK + i) * NPAD + 48], v48, acc[r]);
            }
        }
        __syncthreads();   // all at[] reads done before proj B staging overwrites overlay
        #pragma unroll
        for (int r = 0; r < 13; ++r) {
            int i = ig + 4 * r;
            if (i < NTOK) split_store(acc[r], a_hi, a_lo, (uint32_t)(i * APITCH + c * 2));
        }
    }
    __syncthreads();

    // ---- proj: stage B, gemm, epilogue to global ----
    {
        const float4* wg = (const float4*)proj_w;
        for (int idx = t; idx < 128 * DIMC / 4; idx += NTHREADS) {
            int r = idx >> 5, c = (idx & 31) << 2;
            split_store4(wg[idx], b_hi, b_lo, r, c);
        }
    }
    __syncthreads();

    if (wid < 8) {
        float acc[2][4][4];
        #pragma unroll
        for (int mi = 0; mi < 2; ++mi)
            #pragma unroll
            for (int ni = 0; ni < 4; ++ni)
                #pragma unroll
                for (int q = 0; q < 4; ++q) acc[mi][ni][q] = 0.f;

        hmma_gemm(sb, wid, lane, acc);

        float* og = out + (size_t)bnw * NTOK * DIMC;
        const int m0 = (wid >> 2) * 32, n0 = (wid & 3) * 32;
        #pragma unroll
        for (int mi = 0; mi < 2; ++mi)
            #pragma unroll
            for (int ni = 0; ni < 4; ++ni) {
                int col = n0 + ni * 8 + tc;
                float b0 = proj_b[col];
                float b1 = proj_b[col + 1];
                #pragma unroll
                for (int h2 = 0; h2 < 2; ++h2) {
                    int m = m0 + mi * 16 + tr + h2 * 8;
                    if (m < NTOK) {
                        og[m * DIMC + col]     = acc[mi][ni][2 * h2]     + b0;
                        og[m * DIMC + col + 1] = acc[mi][ni][2 * h2 + 1] + b1;
                    }
                }
            }
    }
}

extern "C" void kernel_launch(void* const* d_in, const int* in_sizes, int n_in,
                              void* d_out, int out_size)
{
    const float* x         = (const float*)d_in[0];
    const float* attn_mask = (const float*)d_in[1];
    const float* qkv_w     = (const float*)d_in[2];
    const float* qkv_b     = (const float*)d_in[3];
    const float* proj_w    = (const float*)d_in[4];
    const float* proj_b    = (const float*)d_in[5];
    const float* rpb_table = (const float*)d_in[6];
    const int*   rpb_index = (const int*)d_in[7];
    float*       out       = (float*)d_out;

    const int bnw = in_sizes[0] / (NTOK * DIMC);   // 8192

    cudaFuncSetAttribute(swin_attn_kernel,
                         cudaFuncAttributeMaxDynamicSharedMemorySize, SMEM_TOTAL);

    swin_attn_kernel<<<bnw, NTHREADS, SMEM_TOTAL>>>(
        x, attn_mask, qkv_w, qkv_b, proj_w, proj_b, rpb_table, rpb_index, out);
}

// round 7
// speedup vs baseline: 2.5625x; 1.0188x over previous
#include <cuda_runtime.h>
#include <cuda_bf16.h>
#include <cstdint>

// WindowAttention fused, R6: QKV+proj on mma.sync bf16 (split hi/lo, 3 products),
// 16-warp GEMM tiling (m32n16/warp), register weight-prefetch pipeline,
// dedicated attention buffer (B tiles live through attention). 512 threads/CTA.

#define NTOK  49
#define DIMC  128
#define NHEAD 4
#define HDIM  32
#define NWIN  64
#define NTHREADS 512

#define QPAD  132
#define KTPAD 53
#define NPAD  52

#define APITCH 272          // bytes per bf16 tile row (136 bf16; 17*16B -> ldmatrix conflict-free)

// smem byte layout (all regions disjoint)
#define SM_AHI 0                          // A hi: 64*272 = 17408
#define SM_ALO (SM_AHI + 64*APITCH)       // A lo
#define SM_BHI (SM_ALO + 64*APITCH)       // B hi: 128*272 = 34816
#define SM_BLO (SM_BHI + 128*APITCH)      // B lo
#define SM_AT  (SM_BLO + 128*APITCH)      // attn[4][49][52] f32 = 40768
#define SM_QS  (SM_AT + NHEAD*NTOK*NPAD*4)
#define SM_KT  (SM_QS + NTOK*QPAD*4)
#define SM_VS  (SM_KT + DIMC*KTPAD*4)
#define SMEM_TOTAL (SM_VS + NTOK*QPAD*4)  // 224096 B

__device__ __forceinline__ uint32_t smem_u32(const void* p) {
    uint32_t a;
    asm("{ .reg .u64 t; cvta.to.shared.u64 t, %1; cvt.u32.u64 %0, t; }" : "=r"(a) : "l"(p));
    return a;
}
__device__ __forceinline__ void ldsm4(uint32_t r[4], uint32_t a) {
    asm volatile("ldmatrix.sync.aligned.m8n8.x4.shared.b16 {%0,%1,%2,%3}, [%4];"
                 : "=r"(r[0]), "=r"(r[1]), "=r"(r[2]), "=r"(r[3]) : "r"(a));
}
__device__ __forceinline__ void mma16816(float c[4], const uint32_t a[4], uint32_t b0, uint32_t b1) {
    asm volatile("mma.sync.aligned.m16n8k16.row.col.f32.bf16.bf16.f32 "
                 "{%0,%1,%2,%3}, {%4,%5,%6,%7}, {%8,%9}, {%0,%1,%2,%3};"
                 : "+f"(c[0]), "+f"(c[1]), "+f"(c[2]), "+f"(c[3])
                 : "r"(a[0]), "r"(a[1]), "r"(a[2]), "r"(a[3]), "r"(b0), "r"(b1));
}

__device__ __forceinline__ void split_store(float v, char* hi, char* lo, uint32_t off) {
    __nv_bfloat16 h = __float2bfloat16(v);
    *(__nv_bfloat16*)(hi + off) = h;
    *(__nv_bfloat16*)(lo + off) = __float2bfloat16(v - __bfloat162float(h));
}
__device__ __forceinline__ void split_store4(float4 v, char* hi, char* lo, int r, int c) {
    uint32_t o = (uint32_t)(r * APITCH + c * 2);
    __nv_bfloat16 h0 = __float2bfloat16(v.x), h1 = __float2bfloat16(v.y);
    __nv_bfloat16 h2 = __float2bfloat16(v.z), h3 = __float2bfloat16(v.w);
    *(__nv_bfloat162*)(hi + o)     = __nv_bfloat162(h0, h1);
    *(__nv_bfloat162*)(hi + o + 4) = __nv_bfloat162(h2, h3);
    __nv_bfloat16 l0 = __float2bfloat16(v.x - __bfloat162float(h0));
    __nv_bfloat16 l1 = __float2bfloat16(v.y - __bfloat162float(h1));
    __nv_bfloat16 l2 = __float2bfloat16(v.z - __bfloat162float(h2));
    __nv_bfloat16 l3 = __float2bfloat16(v.w - __bfloat162float(h3));
    *(__nv_bfloat162*)(lo + o)     = __nv_bfloat162(l0, l1);
    *(__nv_bfloat162*)(lo + o + 4) = __nv_bfloat162(l2, l3);
}

// 16-warp GEMM: C[64x128] = A[64x128] * B[128x128]^T, split-bf16 3-product.
// warp (wid>>3, wid&7) computes m32 x n16. acc[2][2][4].
__device__ __forceinline__ void hmma_gemm(uint32_t sb, int wid, int lane, float acc[2][2][4]) {
    const int m0 = (wid >> 3) * 32;
    const int n0 = (wid & 7) * 16;
    const uint32_t aoff = (uint32_t)((m0 + (lane & 15)) * APITCH + ((lane & 16) >> 1) * 2);
    const uint32_t boff = (uint32_t)((n0 + (lane & 7)) * APITCH + ((lane >> 3) << 3) * 2);
    const uint32_t aHi = sb + SM_AHI + aoff, aLo = sb + SM_ALO + aoff;
    const uint32_t bHi = sb + SM_BHI + boff, bLo = sb + SM_BLO + boff;

    #pragma unroll
    for (int kk = 0; kk < 4; ++kk) {
        const int k0 = kk * 32;
        uint32_t bh[2][4], bl[2][4];
        #pragma unroll
        for (int ni = 0; ni < 2; ++ni) {
            ldsm4(bh[ni], bHi + ni * 8 * APITCH + k0 * 2);
            ldsm4(bl[ni], bLo + ni * 8 * APITCH + k0 * 2);
        }
        #pragma unroll
        for (int half = 0; half < 2; ++half) {
            const int k16 = k0 + half * 16;
            uint32_t ah[2][4], al[2][4];
            ldsm4(ah[0], aHi + k16 * 2);
            ldsm4(ah[1], aHi + 16 * APITCH + k16 * 2);
            ldsm4(al[0], aLo + k16 * 2);
            ldsm4(al[1], aLo + 16 * APITCH + k16 * 2);
            #pragma unroll
            for (int mi = 0; mi < 2; ++mi)
                #pragma unroll
                for (int ni = 0; ni < 2; ++ni) {
                    uint32_t b0 = bh[ni][2 * half], b1 = bh[ni][2 * half + 1];
                    mma16816(acc[mi][ni], ah[mi], b0, b1);
                    mma16816(acc[mi][ni], al[mi], b0, b1);
                    mma16816(acc[mi][ni], ah[mi], bl[ni][2 * half], bl[ni][2 * half + 1]);
                }
        }
    }
}

__global__ void __launch_bounds__(NTHREADS, 1)
swin_attn_kernel(const float* __restrict__ x,
                 const float* __restrict__ attn_mask,
                 const float* __restrict__ qkv_w,
                 const float* __restrict__ qkv_b,
                 const float* __restrict__ proj_w,
                 const float* __restrict__ proj_b,
                 const float* __restrict__ rpb_table,
                 const int*   __restrict__ rpb_index,
                 float*       __restrict__ out)
{
    extern __shared__ char smem[];
    const uint32_t sb = smem_u32(smem);
    char* a_hi = smem + SM_AHI;
    char* a_lo = smem + SM_ALO;
    char* b_hi = smem + SM_BHI;
    char* b_lo = smem + SM_BLO;
    float* at = (float*)(smem + SM_AT);
    float* qs = (float*)(smem + SM_QS);
    float* kt = (float*)(smem + SM_KT);
    float* vs = (float*)(smem + SM_VS);

    const int t = threadIdx.x, wid = t >> 5, lane = t & 31;
    const int bnw = blockIdx.x, win = bnw & (NWIN - 1);
    const int tr = lane >> 2, tc = (lane & 3) * 2;

    // ---- stage A = x (49x128) split bf16 ----
    {
        const float4* xg = (const float4*)(x + (size_t)bnw * NTOK * DIMC);
        for (int idx = t; idx < NTOK * DIMC / 4; idx += NTHREADS) {
            int r = idx >> 5, c = (idx & 31) << 2;
            split_store4(xg[idx], a_hi, a_lo, r, c);
        }
    }
    // ---- stage B chunk 0 ----
    {
        const float4* wg = (const float4*)qkv_w;
        for (int idx = t; idx < 128 * DIMC / 4; idx += NTHREADS) {
            int r = idx >> 5, c = (idx & 31) << 2;
            split_store4(wg[idx], b_hi, b_lo, r, c);
        }
    }
    __syncthreads();

    // ---- QKV chunks (0=q, 1=k, 2=v) with weight prefetch; proj staged in chunk 2 ----
    for (int chunk = 0; chunk < 3; ++chunk) {
        const float4* nw = (const float4*)((chunk < 2) ? (qkv_w + (size_t)(chunk + 1) * 128 * DIMC)
                                                       : proj_w);
        float4 pf[8];
        #pragma unroll
        for (int i = 0; i < 8; ++i) pf[i] = nw[t + i * NTHREADS];   // LDG, hidden by gemm

        float acc[2][2][4];
        #pragma unroll
        for (int mi = 0; mi < 2; ++mi)
            #pragma unroll
            for (int ni = 0; ni < 2; ++ni)
                #pragma unroll
                for (int q = 0; q < 4; ++q) acc[mi][ni][q] = 0.f;

        hmma_gemm(sb, wid, lane, acc);

        // epilogue: fragments -> qs / kt / vs (+bias)
        const int m0 = (wid >> 3) * 32, n0 = (wid & 7) * 16;
        #pragma unroll
        for (int mi = 0; mi < 2; ++mi)
            #pragma unroll
            for (int ni = 0; ni < 2; ++ni) {
                int col = n0 + ni * 8 + tc;
                float b0 = qkv_b[chunk * 128 + col];
                float b1 = qkv_b[chunk * 128 + col + 1];
                #pragma unroll
                for (int h2 = 0; h2 < 2; ++h2) {
                    int m = m0 + mi * 16 + tr + h2 * 8;
                    if (m < NTOK) {
                        float v0 = acc[mi][ni][2 * h2]     + b0;
                        float v1 = acc[mi][ni][2 * h2 + 1] + b1;
                        if (chunk == 0) {
                            qs[m * QPAD + col] = v0; qs[m * QPAD + col + 1] = v1;
                        } else if (chunk == 1) {
                            kt[col * KTPAD + m] = v0; kt[(col + 1) * KTPAD + m] = v1;
                        } else {
                            vs[m * QPAD + col] = v0; vs[m * QPAD + col + 1] = v1;
                        }
                    }
                }
            }
        __syncthreads();   // all warps done reading B tiles
        #pragma unroll
        for (int i = 0; i < 8; ++i) {
            int idx = t + i * NTHREADS;
            split_store4(pf[i], b_hi, b_lo, idx >> 5, (idx & 31) << 2);
        }
        __syncthreads();   // new B ready (after chunk 2: proj weights staged)
    }

    // ---- QK^T * scale + bias + mask (scalar fp32) ----
    {
        const float scale = 0.17677669529663687f;
        const float* mrow = attn_mask + (size_t)win * NTOK * NTOK;
        const int h = t >> 7, ib2 = (t >> 6) & 1, j = t & 63;
        if (j < NTOK) {
            float acc[25];
            #pragma unroll
            for (int r = 0; r < 25; ++r) acc[r] = 0.f;
            #pragma unroll
            for (int d4 = 0; d4 < HDIM; d4 += 4) {
                float k0 = kt[(h * HDIM + d4 + 0) * KTPAD + j];
                float k1 = kt[(h * HDIM + d4 + 1) * KTPAD + j];
                float k2 = kt[(h * HDIM + d4 + 2) * KTPAD + j];
                float k3 = kt[(h * HDIM + d4 + 3) * KTPAD + j];
                #pragma unroll
                for (int r = 0; r < 25; ++r) {
                    int i = min(ib2 + 2 * r, NTOK - 1);
                    float4 qv = *(const float4*)&qs[i * QPAD + h * HDIM + d4];
                    acc[r] = fmaf(qv.x, k0, acc[r]);
                    acc[r] = fmaf(qv.y, k1, acc[r]);
                    acc[r] = fmaf(qv.z, k2, acc[r]);
                    acc[r] = fmaf(qv.w, k3, acc[r]);
                }
            }
            #pragma unroll
            for (int r = 0; r < 25; ++r) {
                int i = ib2 + 2 * r;
                if (i < NTOK) {
                    int ij = i * NTOK + j;
                    float bias = rpb_table[rpb_index[ij] * NHEAD + h];
                    at[(h * NTOK + i) * NPAD + j] = acc[r] * scale + bias + mrow[ij];
                }
            }
        }
    }
    __syncthreads();

    // ---- softmax over 49 ----
    for (int r = wid; r < NHEAD * NTOK; r += 16) {
        float* row = at + r * NPAD;
        float a0 = row[lane];
        float a1 = (lane + 32 < NTOK) ? row[lane + 32] : -1e30f;
        float m = fmaxf(a0, a1);
        #pragma unroll
        for (int o = 16; o; o >>= 1) m = fmaxf(m, __shfl_xor_sync(~0u, m, o));
        float e0 = __expf(a0 - m);
        float e1 = (lane + 32 < NTOK) ? __expf(a1 - m) : 0.f;
        float s = e0 + e1;
        #pragma unroll
        for (int o = 16; o; o >>= 1) s += __shfl_xor_sync(~0u, s, o);
        float inv = 1.f / s;
        row[lane] = e0 * inv;
        if (lane + 32 < NTOK) row[lane + 32] = e1 * inv;
    }
    __syncthreads();

    // ---- AV (scalar) -> y split-stored into A tiles ----
    {
        const int c = t & 127, ig = t >> 7, h = c >> 5;
        float acc[13];
        #pragma unroll
        for (int r = 0; r < 13; ++r) acc[r] = 0.f;
        #pragma unroll 3
        for (int j4 = 0; j4 < 48; j4 += 4) {
            float v0 = vs[(j4 + 0) * QPAD + c];
            float v1 = vs[(j4 + 1) * QPAD + c];
            float v2 = vs[(j4 + 2) * QPAD + c];
            float v3 = vs[(j4 + 3) * QPAD + c];
            #pragma unroll
            for (int r = 0; r < 13; ++r) {
                int i = min(ig + 4 * r, NTOK - 1);
                float4 a4 = *(const float4*)&at[(h * NTOK + i) * NPAD + j4];
                acc[r] = fmaf(a4.x, v0, acc[r]);
                acc[r] = fmaf(a4.y, v1, acc[r]);
                acc[r] = fmaf(a4.z, v2, acc[r]);
                acc[r] = fmaf(a4.w, v3, acc[r]);
            }
        }
        {
            float v48 = vs[48 * QPAD + c];
            #pragma unroll
            for (int r = 0; r < 13; ++r) {
                int i = min(ig + 4 * r, NTOK - 1);
                acc[r] = fmaf(at[(h * NTOK + i) * NPAD + 48], v48, acc[r]);
            }
        }
        #pragma unroll
        for (int r = 0; r < 13; ++r) {
            int i = ig + 4 * r;
            if (i < NTOK) split_store(acc[r], a_hi, a_lo, (uint32_t)(i * APITCH + c * 2));
        }
    }
    __syncthreads();   // y in A tiles; proj B already staged

    // ---- proj gemm + epilogue to global ----
    {
        float acc[2][2][4];
        #pragma unroll
        for (int mi = 0; mi < 2; ++mi)
            #pragma unroll
            for (int ni = 0; ni < 2; ++ni)
                #pragma unroll
                for (int q = 0; q < 4; ++q) acc[mi][ni][q] = 0.f;

        hmma_gemm(sb, wid, lane, acc);

        float* og = out + (size_t)bnw * NTOK * DIMC;
        const int m0 = (wid >> 3) * 32, n0 = (wid & 7) * 16;
        #pragma unroll
        for (int mi = 0; mi < 2; ++mi)
            #pragma unroll
            for (int ni = 0; ni < 2; ++ni) {
                int col = n0 + ni * 8 + tc;
                float b0 = proj_b[col];
                float b1 = proj_b[col + 1];
                #pragma unroll
                for (int h2 = 0; h2 < 2; ++h2) {
                    int m = m0 + mi * 16 + tr + h2 * 8;
                    if (m < NTOK) {
                        og[m * DIMC + col]     = acc[mi][ni][2 * h2]     + b0;
                        og[m * DIMC + col + 1] = acc[mi][ni][2 * h2 + 1] + b1;
                    }
                }
            }
    }
}

extern "C" void kernel_launch(void* const* d_in, const int* in_sizes, int n_in,
                              void* d_out, int out_size)
{
    const float* x         = (const float*)d_in[0];
    const float* attn_mask = (const float*)d_in[1];
    const float* qkv_w     = (const float*)d_in[2];
    const float* qkv_b     = (const float*)d_in[3];
    const float* proj_w    = (const float*)d_in[4];
    const float* proj_b    = (const float*)d_in[5];
    const float* rpb_table = (const float*)d_in[6];
    const int*   rpb_index = (const int*)d_in[7];
    float*       out       = (float*)d_out;

    const int bnw = in_sizes[0] / (NTOK * DIMC);   // 8192

    cudaFuncSetAttribute(swin_attn_kernel,
                         cudaFuncAttributeMaxDynamicSharedMemorySize, SMEM_TOTAL);

    swin_attn_kernel<<<bnw, NTHREADS, SMEM_TOTAL>>>(
        x, attn_mask, qkv_w, qkv_b, proj_w, proj_b, rpb_table, rpb_index, out);
}

// round 9
// speedup vs baseline: 2.7924x; 1.0897x over previous
#include <cuda_runtime.h>
#include <cuda_bf16.h>
#include <cstdint>

// WindowAttention fused, R7: ALL gemms (QKV, S=QK^T, AV, proj) on mma.sync bf16
// split hi/lo 3-product. fp32 only for softmax buffer. One CTA/window, 512 thr.

#define NTOK  49
#define DIMC  128
#define NHEAD 4
#define HDIM  32
#define NWIN  64
#define NTHREADS 512

#define NPAD  52
#define APITCH 272    // bytes/row, 128-col bf16 tiles (17*16B, ldmatrix conflict-free)
#define VPITCH 144    // bytes/row, 64-col bf16 tiles (9*16B, ldmatrix conflict-free)

// smem byte layout
#define SM_XHI 0                         // X/y tile hi: 64*272 = 17408
#define SM_XLO (SM_XHI + 64*APITCH)
#define SM_WHI (SM_XLO + 64*APITCH)      // W tile hi: 128*272 = 34816
#define SM_WLO (SM_WHI + 128*APITCH)
#define SM_AT  SM_WHI                    // attn fp32 [4][49][52] = 40768 (overlays W)
#define SM_QHI (SM_WLO + 128*APITCH)     // Q tile: 64*272
#define SM_QLO (SM_QHI + 64*APITCH)
#define SM_KHI (SM_QLO + 64*APITCH)
#define SM_KLO (SM_KHI + 64*APITCH)
#define SM_PHI SM_QHI                    // P probs: 196*144 = 28224 (overlays Q/K)
#define SM_PLO (SM_PHI + 196*VPITCH)
#define SM_VHI (SM_KLO + 64*APITCH)      // V^T: 128*144 = 18432
#define SM_VLO (SM_VHI + 128*VPITCH)
#define SMEM_TOTAL (SM_VLO + 128*VPITCH) // 210944 B

__device__ __forceinline__ uint32_t smem_u32(const void* p) {
    uint32_t a;
    asm("{ .reg .u64 t; cvta.to.shared.u64 t, %1; cvt.u32.u64 %0, t; }" : "=r"(a) : "l"(p));
    return a;
}
__device__ __forceinline__ void ldsm4(uint32_t r[4], uint32_t a) {
    asm volatile("ldmatrix.sync.aligned.m8n8.x4.shared.b16 {%0,%1,%2,%3}, [%4];"
                 : "=r"(r[0]), "=r"(r[1]), "=r"(r[2]), "=r"(r[3]) : "r"(a));
}
__device__ __forceinline__ void mma16816(float c[4], const uint32_t a[4], uint32_t b0, uint32_t b1) {
    asm volatile("mma.sync.aligned.m16n8k16.row.col.f32.bf16.bf16.f32 "
                 "{%0,%1,%2,%3}, {%4,%5,%6,%7}, {%8,%9}, {%0,%1,%2,%3};"
                 : "+f"(c[0]), "+f"(c[1]), "+f"(c[2]), "+f"(c[3])
                 : "r"(a[0]), "r"(a[1]), "r"(a[2]), "r"(a[3]), "r"(b0), "r"(b1));
}
__device__ __forceinline__ void split_store(float v, char* hi, char* lo, uint32_t off) {
    __nv_bfloat16 h = __float2bfloat16(v);
    *(__nv_bfloat16*)(hi + off) = h;
    *(__nv_bfloat16*)(lo + off) = __float2bfloat16(v - __bfloat162float(h));
}
__device__ __forceinline__ void split_store4p(float4 v, char* hi, char* lo, uint32_t o) {
    __nv_bfloat16 h0 = __float2bfloat16(v.x), h1 = __float2bfloat16(v.y);
    __nv_bfloat16 h2 = __float2bfloat16(v.z), h3 = __float2bfloat16(v.w);
    *(__nv_bfloat162*)(hi + o)     = __nv_bfloat162(h0, h1);
    *(__nv_bfloat162*)(hi + o + 4) = __nv_bfloat162(h2, h3);
    __nv_bfloat16 l0 = __float2bfloat16(v.x - __bfloat162float(h0));
    __nv_bfloat16 l1 = __float2bfloat16(v.y - __bfloat162float(h1));
    __nv_bfloat16 l2 = __float2bfloat16(v.z - __bfloat162float(h2));
    __nv_bfloat16 l3 = __float2bfloat16(v.w - __bfloat162float(h3));
    *(__nv_bfloat162*)(lo + o)     = __nv_bfloat162(l0, l1);
    *(__nv_bfloat162*)(lo + o + 4) = __nv_bfloat162(l2, l3);
}

// C[64x128] = A[64x128] * B[128x128]^T, split-bf16 3-product, 16 warps m32n16.
__device__ __forceinline__ void hmma_gemm_128(uint32_t aHiB, uint32_t aLoB,
                                              uint32_t bHiB, uint32_t bLoB,
                                              int wid, int lane, float acc[2][2][4]) {
    const int m0 = (wid >> 3) * 32, n0 = (wid & 7) * 16;
    const uint32_t aoff = (uint32_t)((m0 + (lane & 15)) * APITCH + (lane & 16));
    const uint32_t boff = (uint32_t)((n0 + (lane & 7)) * APITCH + ((lane >> 3) << 4));
    const uint32_t aHi = aHiB + aoff, aLo = aLoB + aoff;
    const uint32_t bHi = bHiB + boff, bLo = bLoB + boff;
    #pragma unroll
    for (int kk = 0; kk < 4; ++kk) {
        const int k0 = kk * 32;
        uint32_t bh[2][4], bl[2][4];
        #pragma unroll
        for (int ni = 0; ni < 2; ++ni) {
            ldsm4(bh[ni], bHi + ni * 8 * APITCH + k0 * 2);
            ldsm4(bl[ni], bLo + ni * 8 * APITCH + k0 * 2);
        }
        #pragma unroll
        for (int half = 0; half < 2; ++half) {
            const int k16 = k0 + half * 16;
            uint32_t ah[2][4], al[2][4];
            ldsm4(ah[0], aHi + k16 * 2);
            ldsm4(ah[1], aHi + 16 * APITCH + k16 * 2);
            ldsm4(al[0], aLo + k16 * 2);
            ldsm4(al[1], aLo + 16 * APITCH + k16 * 2);
            #pragma unroll
            for (int mi = 0; mi < 2; ++mi)
                #pragma unroll
                for (int ni = 0; ni < 2; ++ni) {
                    uint32_t b0 = bh[ni][2 * half], b1 = bh[ni][2 * half + 1];
                    mma16816(acc[mi][ni], ah[mi], b0, b1);
                    mma16816(acc[mi][ni], al[mi], b0, b1);
                    mma16816(acc[mi][ni], ah[mi], bl[ni][2 * half], bl[ni][2 * half + 1]);
                }
        }
    }
}

__global__ void __launch_bounds__(NTHREADS, 1)
swin_attn_kernel(const float* __restrict__ x,
                 const float* __restrict__ attn_mask,
                 const float* __restrict__ qkv_w,
                 const float* __restrict__ qkv_b,
                 const float* __restrict__ proj_w,
                 const float* __restrict__ proj_b,
                 const float* __restrict__ rpb_table,
                 const int*   __restrict__ rpb_index,
                 float*       __restrict__ out)
{
    extern __shared__ char smem[];
    const uint32_t sb = smem_u32(smem);
    char* xhi = smem + SM_XHI;  char* xlo = smem + SM_XLO;
    char* whi = smem + SM_WHI;  char* wlo = smem + SM_WLO;
    char* qhi = smem + SM_QHI;  char* qlo = smem + SM_QLO;
    char* khi = smem + SM_KHI;  char* klo = smem + SM_KLO;
    char* phi = smem + SM_PHI;  char* plo = smem + SM_PLO;
    char* vhi = smem + SM_VHI;  char* vlo = smem + SM_VLO;
    float* at = (float*)(smem + SM_AT);

    const int t = threadIdx.x, wid = t >> 5, lane = t & 31;
    const int bnw = blockIdx.x, win = bnw & (NWIN - 1);
    const int tr = lane >> 2, tc = (lane & 3) * 2;

    // ---- zero V^T pad cols 48..63 (hi & lo); stage X; stage W=Wq ----
    for (int idx = t; idx < 128 * 8; idx += NTHREADS) {
        int r = idx >> 3, w4 = idx & 7;
        *(uint32_t*)(vhi + r * VPITCH + 96 + w4 * 4) = 0u;
        *(uint32_t*)(vlo + r * VPITCH + 96 + w4 * 4) = 0u;
    }
    {
        const float4* xg = (const float4*)(x + (size_t)bnw * NTOK * DIMC);
        for (int idx = t; idx < NTOK * DIMC / 4; idx += NTHREADS) {
            int r = idx >> 5, c = (idx & 31) << 2;
            split_store4p(xg[idx], xhi, xlo, (uint32_t)(r * APITCH + c * 2));
        }
        const float4* wg = (const float4*)qkv_w;
        for (int idx = t; idx < 128 * DIMC / 4; idx += NTHREADS) {
            int r = idx >> 5, c = (idx & 31) << 2;
            split_store4p(wg[idx], whi, wlo, (uint32_t)(r * APITCH + c * 2));
        }
    }
    __syncthreads();

    // ---- QKV chunks 0=q,1=k,2=v ----
    for (int chunk = 0; chunk < 3; ++chunk) {
        float4 pf[8];
        if (chunk < 2) {
            const float4* nw = (const float4*)(qkv_w + (size_t)(chunk + 1) * 128 * DIMC);
            #pragma unroll
            for (int i = 0; i < 8; ++i) pf[i] = nw[t + i * NTHREADS];
        }
        float acc[2][2][4];
        #pragma unroll
        for (int mi = 0; mi < 2; ++mi)
            #pragma unroll
            for (int ni = 0; ni < 2; ++ni)
                #pragma unroll
                for (int q = 0; q < 4; ++q) acc[mi][ni][q] = 0.f;

        hmma_gemm_128(sb + SM_XHI, sb + SM_XLO, sb + SM_WHI, sb + SM_WLO, wid, lane, acc);

        const int m0 = (wid >> 3) * 32, n0 = (wid & 7) * 16;
        #pragma unroll
        for (int mi = 0; mi < 2; ++mi)
            #pragma unroll
            for (int ni = 0; ni < 2; ++ni) {
                int col = n0 + ni * 8 + tc;
                float b0 = qkv_b[chunk * 128 + col];
                float b1 = qkv_b[chunk * 128 + col + 1];
                #pragma unroll
                for (int h2 = 0; h2 < 2; ++h2) {
                    int m = m0 + mi * 16 + tr + h2 * 8;
                    if (m < NTOK) {
                        float v0 = acc[mi][ni][2 * h2] + b0;
                        float v1 = acc[mi][ni][2 * h2 + 1] + b1;
                        if (chunk == 0) {
                            split_store(v0, qhi, qlo, (uint32_t)(m * APITCH + col * 2));
                            split_store(v1, qhi, qlo, (uint32_t)(m * APITCH + (col + 1) * 2));
                        } else if (chunk == 1) {
                            split_store(v0, khi, klo, (uint32_t)(m * APITCH + col * 2));
                            split_store(v1, khi, klo, (uint32_t)(m * APITCH + (col + 1) * 2));
                        } else {   // V^T: row=dim col, col=token
                            split_store(v0, vhi, vlo, (uint32_t)(col * VPITCH + m * 2));
                            split_store(v1, vhi, vlo, (uint32_t)((col + 1) * VPITCH + m * 2));
                        }
                    }
                }
            }
        __syncthreads();
        if (chunk < 2) {
            #pragma unroll
            for (int i = 0; i < 8; ++i) {
                int idx = t + i * NTHREADS;
                split_store4p(pf[i], whi, wlo, (uint32_t)((idx >> 5) * APITCH + ((idx & 31) << 2) * 2));
            }
            __syncthreads();
        }
    }

    // ---- S = Q K^T per head (K=32), epilogue -> at (fp32, scale+bias+mask) ----
    {
        const int h = wid >> 2, sub = wid & 3;
        const int ms = (sub >> 1) * 32, ns = (sub & 1) * 32;
        const uint32_t aoff = (uint32_t)((ms + (lane & 15)) * APITCH + (lane & 16) + h * 64);
        const uint32_t boff = (uint32_t)((ns + (lane & 7)) * APITCH + ((lane >> 3) << 4) + h * 64);
        const uint32_t aHi = sb + SM_QHI + aoff, aLo = sb + SM_QLO + aoff;
        const uint32_t bHi = sb + SM_KHI + boff, bLo = sb + SM_KLO + boff;

        float accS[2][4][4];
        #pragma unroll
        for (int mi = 0; mi < 2; ++mi)
            #pragma unroll
            for (int ni = 0; ni < 4; ++ni)
                #pragma unroll
                for (int q = 0; q < 4; ++q) accS[mi][ni][q] = 0.f;

        uint32_t bh[4][4], bl[4][4];
        #pragma unroll
        for (int ni = 0; ni < 4; ++ni) {
            ldsm4(bh[ni], bHi + ni * 8 * APITCH);
            ldsm4(bl[ni], bLo + ni * 8 * APITCH);
        }
        #pragma unroll
        for (int half = 0; half < 2; ++half) {
            uint32_t ah[2][4], al[2][4];
            ldsm4(ah[0], aHi + half * 32);
            ldsm4(ah[1], aHi + 16 * APITCH + half * 32);
            ldsm4(al[0], aLo + half * 32);
            ldsm4(al[1], aLo + 16 * APITCH + half * 32);
            #pragma unroll
            for (int mi = 0; mi < 2; ++mi)
                #pragma unroll
                for (int ni = 0; ni < 4; ++ni) {
                    uint32_t b0 = bh[ni][2 * half], b1 = bh[ni][2 * half + 1];
                    mma16816(accS[mi][ni], ah[mi], b0, b1);
                    mma16816(accS[mi][ni], al[mi], b0, b1);
                    mma16816(accS[mi][ni], ah[mi], bl[ni][2 * half], bl[ni][2 * half + 1]);
                }
        }

        const float scale = 0.17677669529663687f;
        const float* mrow = attn_mask + (size_t)win * NTOK * NTOK;
        #pragma unroll
        for (int mi = 0; mi < 2; ++mi)
            #pragma unroll
            for (int ni = 0; ni < 4; ++ni)
                #pragma unroll
                for (int q = 0; q < 4; ++q) {
                    int i = ms + mi * 16 + tr + (q >> 1) * 8;
                    int j = ns + ni * 8 + tc + (q & 1);
                    if (i < NTOK && j < NTOK) {
                        int ij = i * NTOK + j;
                        at[(h * NTOK + i) * NPAD + j] =
                            accS[mi][ni][q] * scale + rpb_table[rpb_index[ij] * NHEAD + h] + mrow[ij];
                    }
                }
    }
    __syncthreads();

    // ---- softmax (fp32) ----
    for (int r = wid; r < NHEAD * NTOK; r += 16) {
        float* row = at + r * NPAD;
        float a0 = row[lane];
        float a1 = (lane + 32 < NTOK) ? row[lane + 32] : -1e30f;
        float m = fmaxf(a0, a1);
        #pragma unroll
        for (int o = 16; o; o >>= 1) m = fmaxf(m, __shfl_xor_sync(~0u, m, o));
        float e0 = __expf(a0 - m);
        float e1 = (lane + 32 < NTOK) ? __expf(a1 - m) : 0.f;
        float s = e0 + e1;
        #pragma unroll
        for (int o = 16; o; o >>= 1) s += __shfl_xor_sync(~0u, s, o);
        float inv = 1.f / s;
        row[lane] = e0 * inv;
        if (lane + 32 < NTOK) row[lane + 32] = e1 * inv;
    }
    __syncthreads();

    // ---- P store (at -> split bf16, j-pad zeroed); prefetch proj weights ----
    float4 pf2[8];
    {
        const float4* nw = (const float4*)proj_w;
        #pragma unroll
        for (int i = 0; i < 8; ++i) pf2[i] = nw[t + i * NTHREADS];
    }
    for (int idx = t; idx < 196 * 64; idx += NTHREADS) {
        int j = idx & 63, r = idx >> 6;       // r = h*49 + i
        float v = (j < NTOK) ? at[r * NPAD + j] : 0.f;
        split_store(v, phi, plo, (uint32_t)(r * VPITCH + j * 2));
    }
    __syncthreads();   // at dead from here

    // ---- store proj weights -> W (clobbers at); AV gemm ----
    #pragma unroll
    for (int i = 0; i < 8; ++i) {
        int idx = t + i * NTHREADS;
        split_store4p(pf2[i], whi, wlo, (uint32_t)((idx >> 5) * APITCH + ((idx & 31) << 2) * 2));
    }
    {
        const int h = wid >> 2, sub = wid & 3;
        const int ms = (sub >> 1) * 32, ns2 = (sub & 1) * 16;
        const uint32_t aoff = (uint32_t)((h * NTOK + ms + (lane & 15)) * VPITCH + (lane & 16));
        const uint32_t boff = (uint32_t)((h * HDIM + ns2 + (lane & 7)) * VPITCH + ((lane >> 3) << 4));
        const uint32_t aHi = sb + SM_PHI + aoff, aLo = sb + SM_PLO + aoff;
        const uint32_t bHi = sb + SM_VHI + boff, bLo = sb + SM_VLO + boff;

        float accv[2][2][4];
        #pragma unroll
        for (int mi = 0; mi < 2; ++mi)
            #pragma unroll
            for (int ni = 0; ni < 2; ++ni)
                #pragma unroll
                for (int q = 0; q < 4; ++q) accv[mi][ni][q] = 0.f;

        #pragma unroll
        for (int kk = 0; kk < 2; ++kk) {
            const int k0 = kk * 32;
            uint32_t bh[2][4], bl[2][4];
            #pragma unroll
            for (int ni = 0; ni < 2; ++ni) {
                ldsm4(bh[ni], bHi + ni * 8 * VPITCH + k0 * 2);
                ldsm4(bl[ni], bLo + ni * 8 * VPITCH + k0 * 2);
            }
            #pragma unroll
            for (int half = 0; half < 2; ++half) {
                const int k16 = k0 + half * 16;
                uint32_t ah[2][4], al[2][4];
                ldsm4(ah[0], aHi + k16 * 2);
                ldsm4(ah[1], aHi + 16 * VPITCH + k16 * 2);
                ldsm4(al[0], aLo + k16 * 2);
                ldsm4(al[1], aLo + 16 * VPITCH + k16 * 2);
                #pragma unroll
                for (int mi = 0; mi < 2; ++mi)
                    #pragma unroll
                    for (int ni = 0; ni < 2; ++ni) {
                        uint32_t b0 = bh[ni][2 * half], b1 = bh[ni][2 * half + 1];
                        mma16816(accv[mi][ni], ah[mi], b0, b1);
                        mma16816(accv[mi][ni], al[mi], b0, b1);
                        mma16816(accv[mi][ni], ah[mi], bl[ni][2 * half], bl[ni][2 * half + 1]);
                    }
            }
        }
        // epilogue: y -> X tiles (split bf16)
        #pragma unroll
        for (int mi = 0; mi < 2; ++mi)
            #pragma unroll
            for (int ni = 0; ni < 2; ++ni)
                #pragma unroll
                for (int q = 0; q < 4; ++q) {
                    int i = ms + mi * 16 + tr + (q >> 1) * 8;
                    if (i < NTOK) {
                        int col = h * HDIM + ns2 + ni * 8 + tc + (q & 1);
                        split_store(accv[mi][ni][q], xhi, xlo, (uint32_t)(i * APITCH + col * 2));
                    }
                }
    }
    __syncthreads();

    // ---- proj gemm + epilogue to global ----
    {
        float acc[2][2][4];
        #pragma unroll
        for (int mi = 0; mi < 2; ++mi)
            #pragma unroll
            for (int ni = 0; ni < 2; ++ni)
                #pragma unroll
                for (int q = 0; q < 4; ++q) acc[mi][ni][q] = 0.f;

        hmma_gemm_128(sb + SM_XHI, sb + SM_XLO, sb + SM_WHI, sb + SM_WLO, wid, lane, acc);

        float* og = out + (size_t)bnw * NTOK * DIMC;
        const int m0 = (wid >> 3) * 32, n0 = (wid & 7) * 16;
        #pragma unroll
        for (int mi = 0; mi < 2; ++mi)
            #pragma unroll
            for (int ni = 0; ni < 2; ++ni) {
                int col = n0 + ni * 8 + tc;
                float b0 = proj_b[col], b1 = proj_b[col + 1];
                #pragma unroll
                for (int h2 = 0; h2 < 2; ++h2) {
                    int m = m0 + mi * 16 + tr + h2 * 8;
                    if (m < NTOK) {
                        og[m * DIMC + col]     = acc[mi][ni][2 * h2]     + b0;
                        og[m * DIMC + col + 1] = acc[mi][ni][2 * h2 + 1] + b1;
                    }
                }
            }
    }
}

extern "C" void kernel_launch(void* const* d_in, const int* in_sizes, int n_in,
                              void* d_out, int out_size)
{
    const float* x         = (const float*)d_in[0];
    const float* attn_mask = (const float*)d_in[1];
    const float* qkv_w     = (const float*)d_in[2];
    const float* qkv_b     = (const float*)d_in[3];
    const float* proj_w    = (const float*)d_in[4];
    const float* proj_b    = (const float*)d_in[5];
    const float* rpb_table = (const float*)d_in[6];
    const int*   rpb_index = (const int*)d_in[7];
    float*       out       = (float*)d_out;

    const int bnw = in_sizes[0] / (NTOK * DIMC);   // 8192

    cudaFuncSetAttribute(swin_attn_kernel,
                         cudaFuncAttributeMaxDynamicSharedMemorySize, SMEM_TOTAL);

    swin_attn_kernel<<<bnw, NTHREADS, SMEM_TOTAL>>>(
        x, attn_mask, qkv_w, qkv_b, proj_w, proj_b, rpb_table, rpb_index, out);
}